// round 2
// baseline (speedup 1.0000x reference)
#include <cuda_runtime.h>

#define TB 512

static __device__ __forceinline__ float4 f4mul(float4 a, float4 b) {
    return make_float4(a.x * b.x, a.y * b.y, a.z * b.z, a.w * b.w);
}
static __device__ __forceinline__ void f4fma(float4& acc, float s, float4 v) {
    acc.x = fmaf(s, v.x, acc.x);
    acc.y = fmaf(s, v.y, acc.y);
    acc.z = fmaf(s, v.z, acc.z);
    acc.w = fmaf(s, v.w, acc.w);
}

// Problem constants
// B=256, LC=400, LQ=50, D=128
// Outputs (in order): result (B,LC,4D), S_bar (B,LC,LQ), S_T (B,LQ,LC)

__global__ __launch_bounds__(TB, 1)
void cqa_kernel(const float* __restrict__ g_xc, const float* __restrict__ g_xq,
                const float* __restrict__ g_W0, const float* __restrict__ g_W1,
                const float* __restrict__ g_W2, const int* __restrict__ g_clen,
                const int* __restrict__ g_qlen, float* __restrict__ out)
{
    constexpr int LC = 400, LQ = 50, D = 128, NB = 256;
    constexpr int SS = 51;    // S row stride (odd -> conflict-free column walks)
    constexpr int XQS = 132;  // xq row stride (float4-aligned, padded)
    constexpr int BTS = 401;  // xc2T row stride (odd -> conflict-free transpose store)
    constexpr int BCS = 132;  // xc chunk row stride
    constexpr int AS = 132;   // A row stride

    extern __shared__ float sm[];
    float* S    = sm;                 // 400*51   = 20400
    float* xq   = S + LC * SS;        // 50*132   = 6600
    float* buf  = xq + LQ * XQS;      // 12832 (32*401 transpose / 64*132 chunk)
    float* A    = buf + 12832;        // 50*132   = 6600
    float* stb  = A + LQ * AS;        // 50*64    = 3200
    float* sc   = stb + 3200;         // 400
    float* sq   = sc + LC;            // 64
    float* mxc  = sq + 64;            // 64
    float* invc = mxc + 64;           // 64
    float* W0s  = invc + 64;          // 128
    float* W1s  = W0s + D;            // 128
    float* W2s  = W1s + D;            // 128
    // total = 50608 floats = 202432 bytes

    const int b    = blockIdx.x;
    const int t    = threadIdx.x;
    const int lane = t & 31;
    const int wid  = t >> 5;

    const float* xcb = g_xc + (size_t)b * LC * D;
    const float* xqb = g_xq + (size_t)b * LQ * D;
    const int clen = g_clen[b];
    const int qlen = g_qlen[b];

    float* outRes = out;
    float* outSB  = out + (size_t)NB * LC * 4 * D;           // 52428800
    float* outST  = outSB + (size_t)NB * LC * LQ;            // +5120000

    // ---------------- Phase 0: load weights, x_ques; init; s_q ----------------
    if (t < D) { W0s[t] = g_W0[t]; W1s[t] = g_W1[t]; W2s[t] = g_W2[t]; }
    for (int i = t; i < LQ * D; i += TB) {
        int q = i >> 7, d = i & 127;
        xq[q * XQS + d] = xqb[i];
    }
    for (int i = t; i < LC; i += TB) sc[i] = 0.f;
    __syncthreads();

    for (int q = wid; q < LQ; q += 16) {
        float4 v = *(const float4*)&xq[q * XQS + lane * 4];
        float4 w = *(const float4*)&W1s[lane * 4];
        float p = v.x * w.x + v.y * w.y + v.z * w.z + v.w * w.w;
        #pragma unroll
        for (int o = 16; o; o >>= 1) p += __shfl_xor_sync(0xffffffffu, p, o);
        if (lane == 0) sq[q] = p;
    }

    // ---------------- Phase 1: S[c,q] = sc + sq + (xc*W2).xq ----------------
    // Block-wide register tile: 500 active threads, each owns 8c x 5q.
    float acc[8][5];
    #pragma unroll
    for (int i = 0; i < 8; i++)
        #pragma unroll
        for (int j = 0; j < 5; j++) acc[i][j] = 0.f;

    const int ct = t % 50;
    const int qt = t / 50;
    const bool act = (t < 500);

    for (int dc = 0; dc < 4; ++dc) {
        const int d0 = dc * 32;
        const float w0v = W0s[d0 + lane];
        const float w2v = W2s[d0 + lane];
        __syncthreads();  // previous iter readers done with buf
        // load transposed slice xc2T[dd][c] = xc[c][d0+dd]*W2, fold s_c via shuffle
        for (int i = t; i < LC * 32; i += TB) {
            int c = i >> 5;  // warp-uniform; dd == lane
            float v = xcb[c * D + d0 + lane];
            buf[lane * BTS + c] = v * w2v;
            float p = v * w0v;
            #pragma unroll
            for (int o = 16; o; o >>= 1) p += __shfl_xor_sync(0xffffffffu, p, o);
            if (lane == 0) sc[c] += p;
        }
        __syncthreads();
        if (act) {
            #pragma unroll 4
            for (int dd = 0; dd < 32; ++dd) {
                float xcv[8], xqv[5];
                #pragma unroll
                for (int i = 0; i < 8; i++) xcv[i] = buf[dd * BTS + ct + 50 * i];
                #pragma unroll
                for (int j = 0; j < 5; j++) xqv[j] = xq[(qt + 10 * j) * XQS + d0 + dd];
                #pragma unroll
                for (int i = 0; i < 8; i++)
                    #pragma unroll
                    for (int j = 0; j < 5; j++)
                        acc[i][j] = fmaf(xcv[i], xqv[j], acc[i][j]);
            }
        }
    }
    __syncthreads();
    if (act) {
        #pragma unroll
        for (int i = 0; i < 8; i++) {
            int c = ct + 50 * i;
            float scv = sc[c];
            #pragma unroll
            for (int j = 0; j < 5; j++) {
                int q = qt + 10 * j;
                S[c * SS + q] = acc[i][j] + scv + sq[q];
            }
        }
    }
    __syncthreads();

    // ---------------- Phase 2: column (over c) softmax stats, c-masked -------
    for (int q = wid; q < LQ; q += 16) {
        float m = -1e30f, s = 0.f;
        for (int c = lane; c < LC; c += 32) {
            if (c < clen) {
                float v = S[c * SS + q];
                if (v > m) { s = s * __expf(m - v) + 1.f; m = v; }
                else       { s += __expf(v - m); }
            }
        }
        #pragma unroll
        for (int o = 16; o; o >>= 1) {
            float m2 = __shfl_xor_sync(0xffffffffu, m, o);
            float s2 = __shfl_xor_sync(0xffffffffu, s, o);
            if (m2 > m) { s = s * __expf(m - m2) + s2; m = m2; }
            else        { s += s2 * __expf(m2 - m); }
        }
        if (lane == 0) { mxc[q] = m; invc[q] = 1.f / s; }
    }
    __syncthreads();

    // ---------------- Phase 3: S_T (write out) + A = S_T @ x_cont ------------
    {
        const int d4 = lane * 4;
        const int qg = wid;
        const int nq = (qg < 2) ? 4 : 3;  // q = qg + 16*j covers 0..49
        float4 accA[4];
        #pragma unroll
        for (int j = 0; j < 4; j++) accA[j] = make_float4(0.f, 0.f, 0.f, 0.f);

        for (int c0 = 0; c0 < LC; c0 += 64) {
            const int CH = (LC - c0 >= 64) ? 64 : (LC - c0);  // 64,...,16
            __syncthreads();  // prior readers of buf/stb done
            for (int i = t; i < CH * D; i += TB) {
                int cc = i >> 7, d = i & 127;
                buf[cc * BCS + d] = xcb[(c0 + cc) * D + d];
            }
            if (CH == 64) {
                for (int i = t; i < LQ * 64; i += TB) {
                    int q = i >> 6, cc = i & 63, c = c0 + cc;
                    float v = 0.f;
                    if (c < clen) v = __expf(S[c * SS + q] - mxc[q]) * invc[q];
                    stb[q * 64 + cc] = v;
                    outST[((size_t)b * LQ + q) * LC + c] = v;
                }
            } else {
                for (int i = t; i < LQ * 16; i += TB) {
                    int q = i >> 4, cc = i & 15, c = c0 + cc;
                    float v = 0.f;
                    if (c < clen) v = __expf(S[c * SS + q] - mxc[q]) * invc[q];
                    stb[q * 64 + cc] = v;
                    outST[((size_t)b * LQ + q) * LC + c] = v;
                }
            }
            __syncthreads();
            for (int cc = 0; cc < CH; ++cc) {
                float4 xcv = *(const float4*)&buf[cc * BCS + d4];
                #pragma unroll
                for (int j = 0; j < 4; j++) {
                    if (j < nq) {
                        float st = stb[(qg + 16 * j) * 64 + cc];
                        f4fma(accA[j], st, xcv);
                    }
                }
            }
        }
        #pragma unroll
        for (int j = 0; j < 4; j++)
            if (j < nq) *(float4*)&A[(qg + 16 * j) * AS + d4] = accA[j];
    }
    __syncthreads();

    // ---------------- Phase 4: row softmax -> S_bar in place (q-masked) ------
    for (int c = wid; c < LC; c += 16) {
        const int q2 = lane + 32;
        float v1 = S[c * SS + lane];
        float v2 = (q2 < LQ) ? S[c * SS + q2] : 0.f;
        float m = (lane < qlen) ? v1 : -1e30f;
        if (q2 < LQ && q2 < qlen) m = fmaxf(m, v2);
        #pragma unroll
        for (int o = 16; o; o >>= 1) m = fmaxf(m, __shfl_xor_sync(0xffffffffu, m, o));
        float e1 = (lane < qlen) ? __expf(v1 - m) : 0.f;
        float e2 = (q2 < LQ && q2 < qlen) ? __expf(v2 - m) : 0.f;
        float s = e1 + e2;
        #pragma unroll
        for (int o = 16; o; o >>= 1) s += __shfl_xor_sync(0xffffffffu, s, o);
        float r = 1.f / s;
        e1 *= r; e2 *= r;
        S[c * SS + lane] = e1;
        outSB[((size_t)b * LC + c) * LQ + lane] = e1;
        if (q2 < LQ) {
            S[c * SS + q2] = e2;
            outSB[((size_t)b * LC + c) * LQ + q2] = e2;
        }
    }
    __syncthreads();

    // ---------------- Phase 6: c2q = Sbar@xq, q2c = Sbar@A, fused concat -----
    {
        const int d4 = lane * 4;
        const int cg = wid;
        for (int c0 = 0; c0 < LC; c0 += 128) {
            const int KC = (LC - c0 >= 128) ? 8 : 1;  // c = c0 + cg + 16k
            float4 a1[8], a2[8];
            #pragma unroll
            for (int k = 0; k < 8; k++) {
                a1[k] = make_float4(0.f, 0.f, 0.f, 0.f);
                a2[k] = make_float4(0.f, 0.f, 0.f, 0.f);
            }
            for (int q = 0; q < LQ; ++q) {
                float4 xqv = *(const float4*)&xq[q * XQS + d4];
                float4 av  = *(const float4*)&A[q * AS + d4];
                #pragma unroll
                for (int k = 0; k < 8; k++) {
                    if (k < KC) {
                        float sb = S[(c0 + cg + 16 * k) * SS + q];  // broadcast
                        f4fma(a1[k], sb, xqv);
                        f4fma(a2[k], sb, av);
                    }
                }
            }
            #pragma unroll
            for (int k = 0; k < 8; k++) {
                if (k < KC) {
                    int c = c0 + cg + 16 * k;
                    float4 xcv = *(const float4*)&xcb[c * D + d4];
                    size_t base = ((size_t)b * LC + c) * (4 * D);
                    *(float4*)&outRes[base + d4]           = xcv;
                    *(float4*)&outRes[base + 128 + d4]     = a1[k];
                    *(float4*)&outRes[base + 256 + d4]     = f4mul(xcv, a1[k]);
                    *(float4*)&outRes[base + 384 + d4]     = f4mul(xcv, a2[k]);
                }
            }
        }
    }
}

extern "C" void kernel_launch(void* const* d_in, const int* in_sizes, int n_in,
                              void* d_out, int out_size)
{
    const float* xc  = (const float*)d_in[0];
    const float* xqg = (const float*)d_in[1];
    const float* W0  = (const float*)d_in[2];
    const float* W1  = (const float*)d_in[3];
    const float* W2  = (const float*)d_in[4];
    const int* clen  = (const int*)d_in[5];
    const int* qlen  = (const int*)d_in[6];
    float* out = (float*)d_out;

    const size_t smem = 50608u * sizeof(float);  // 202432 B
    cudaFuncSetAttribute(cqa_kernel, cudaFuncAttributeMaxDynamicSharedMemorySize,
                         (int)smem);
    cqa_kernel<<<256, TB, smem>>>(xc, xqg, W0, W1, W2, clen, qlen, out);
}